// round 15
// baseline (speedup 1.0000x reference)
#include <cuda_runtime.h>
#include <cuda_fp16.h>
#include <cstdint>

#define SVOL   262144        // 64^3
#define NVOX   1048576       // 4 * SVOL
#define NPAIR  12
#define INF_F  1e12f

// ---- device scratch ----
__device__ unsigned short g_u[24 * SVOL];   // pass-2 squared dists (exact ints <= 11907; 65535 = INF sentinel)
__device__ __half g_probs[NPAIR * SVOL];    // probs classes 1..3: [b][cls-1][d][h][w]
__device__ double g_Sp[16];
__device__ double g_TP[16];
__device__ unsigned g_cnt[16];
__device__ double g_focal;
__device__ double g_bound[NPAIR];

// ------------------------------------------------------------------
__global__ void kZero() {
    int t = threadIdx.x;
    if (t < 16) { g_Sp[t] = 0.0; g_TP[t] = 0.0; g_cnt[t] = 0u; }
    if (t < NPAIR) g_bound[t] = 0.0;
    if (t == 0) g_focal = 0.0;
}

__device__ __forceinline__ float wredsum(float v) {
    v += __shfl_xor_sync(0xffffffffu, v, 16);
    v += __shfl_xor_sync(0xffffffffu, v, 8);
    v += __shfl_xor_sync(0xffffffffu, v, 4);
    v += __shfl_xor_sync(0xffffffffu, v, 2);
    v += __shfl_xor_sync(0xffffffffu, v, 1);
    return v;
}
__device__ __forceinline__ float wredmax(float v) {
    v = fmaxf(v, __shfl_xor_sync(0xffffffffu, v, 16));
    v = fmaxf(v, __shfl_xor_sync(0xffffffffu, v, 8));
    v = fmaxf(v, __shfl_xor_sync(0xffffffffu, v, 4));
    v = fmaxf(v, __shfl_xor_sync(0xffffffffu, v, 2));
    v = fmaxf(v, __shfl_xor_sync(0xffffffffu, v, 1));
    return v;
}

__device__ __forceinline__ float nearestSq(unsigned long long m, int i) {
    if (m == 0ull) return INF_F;
    unsigned long long lo = m << (63 - i);   // bits j<=i
    unsigned long long hi = m >> i;          // bits j>=i
    int dup = lo ? __clzll(lo) : 1000;
    int ddn = hi ? (__ffsll(hi) - 1) : 1000;
    int d = min(dup, ddn);
    return (float)(d * d);
}

// ------------------------------------------------------------------
// Fused kernel: blocks [0,4096) do softmax/focal/Tversky stats;
// blocks [4096, 4096+1536) do pass1+pass2 EDT for one (vol, d) plane.
__global__ void __launch_bounds__(256) kFused(const float* __restrict__ preds,
                                              const int* __restrict__ targets) {
    __shared__ float g[4096];   // pass12: g[h*64+w] = f(h,w) + h^2
    __shared__ int   Mw[64];
    __shared__ float ssp[4], stp[4], sfo;
    __shared__ unsigned scnt[4];

    int tid = threadIdx.x, lane = tid & 31;

    if (blockIdx.x < 4096) {
        // ================= stats role =================
        if (tid < 4) { ssp[tid] = 0.f; stp[tid] = 0.f; scnt[tid] = 0u; }
        if (tid == 0) sfo = 0.f;
        __syncthreads();

        int v = blockIdx.x * 256 + tid;
        int b = v >> 18;
        int s = v & (SVOL - 1);

        const float* p = preds + ((size_t)b << 20) + s;
        float x0 = p[0], x1 = p[SVOL], x2 = p[2 * SVOL], x3 = p[3 * SVOL];
        float m = fmaxf(fmaxf(x0, x1), fmaxf(x2, x3));
        float e0 = __expf(x0 - m), e1 = __expf(x1 - m);
        float e2 = __expf(x2 - m), e3 = __expf(x3 - m);
        float Z = e0 + e1 + e2 + e3;
        float inv = 1.0f / Z;
        float p0 = e0 * inv, p1 = e1 * inv, p2 = e2 * inv, p3 = e3 * inv;

        int t = targets[v];
        float lz = __logf(Z);
        float xt = (t == 0) ? x0 : (t == 1) ? x1 : (t == 2) ? x2 : x3;
        float pt = (t == 0) ? p0 : (t == 1) ? p1 : (t == 2) ? p2 : p3;
        float ce = -(xt - m - lz);
        float om = 1.0f - pt;
        float fo = om * om * ce;

        size_t pb = (size_t)(b * 3) * SVOL + s;
        g_probs[pb]            = __float2half(p1);
        g_probs[pb + SVOL]     = __float2half(p2);
        g_probs[pb + 2 * SVOL] = __float2half(p3);

        float sp[4] = { p0, p1, p2, p3 };
        #pragma unroll
        for (int c = 0; c < 4; c++) {
            unsigned bal = __ballot_sync(0xffffffffu, t == c);
            float spv = wredsum(sp[c]);
            float tpv = wredsum((t == c) ? pt : 0.0f);
            if (lane == 0) {
                atomicAdd(&ssp[c], spv);
                atomicAdd(&stp[c], tpv);
                atomicAdd(&scnt[c], (unsigned)__popc(bal));
            }
        }
        float fr = wredsum(fo);
        if (lane == 0) atomicAdd(&sfo, fr);
        __syncthreads();

        if (tid < 4) {
            atomicAdd(&g_Sp[b * 4 + tid], (double)ssp[tid]);
            atomicAdd(&g_TP[b * 4 + tid], (double)stp[tid]);
            atomicAdd(&g_cnt[b * 4 + tid], scnt[tid]);
        }
        if (tid == 4) atomicAdd(&g_focal, (double)sfo);
        return;
    }

    // ================= pass1 + pass2 role =================
    int bb = blockIdx.x - 4096;           // 0..1535
    int vol = bb >> 6, d = bb & 63;       // vol 0..23
    int v12 = (vol >= 12) ? vol - 12 : vol;
    int b = v12 / 3, cls = v12 % 3 + 1;
    bool invm = (vol >= 12);
    const int* tp = targets + ((size_t)b << 18) + ((size_t)d << 12);
    int wid = tid >> 5;

    if (tid < 64) Mw[tid] = 0;
    __syncthreads();

    // pass 1 (W axis): each warp handles lines h = wid*8 + i
    float mx0 = 0.f, mx1 = 0.f;
    #pragma unroll
    for (int i = 0; i < 8; i++) {
        int h = wid * 8 + i;
        int t0 = tp[(h << 6) + lane];
        int t1 = tp[(h << 6) + lane + 32];
        unsigned b0 = __ballot_sync(0xffffffffu, t0 == cls);
        unsigned b1 = __ballot_sync(0xffffffffu, t1 == cls);
        unsigned long long mm = (unsigned long long)b0 | ((unsigned long long)b1 << 32);
        if (invm) mm = ~mm;
        float f0 = nearestSq(mm, lane);
        float f1 = nearestSq(mm, lane + 32);
        float hh = (float)(h * h);
        g[(h << 6) + lane]      = f0 + hh;
        g[(h << 6) + lane + 32] = f1 + hh;
        mx0 = fmaxf(mx0, f0);
        mx1 = fmaxf(mx1, f1);
    }
    atomicMax(&Mw[lane],      __float_as_int(mx0));
    atomicMax(&Mw[lane + 32], __float_as_int(mx1));
    __syncthreads();

    // pass 2 (H axis): windowed min-plus; thread outputs h in [H0, H0+15]
    int w = tid & 63, H0 = (tid >> 6) << 4;
    float M = wredmax(__int_as_float(Mw[w]));
    int r = (int)sqrtf(M) + 1;
    int jlo = max(0, H0 - r), jhi = min(63, H0 + 15 + r);
    float n2m0 = -2.0f * (float)H0;

    float best[16];
    #pragma unroll
    for (int k = 0; k < 16; k++) best[k] = 3e12f;
    float jf = (float)jlo;
    for (int j = jlo; j <= jhi; j++) {
        float gv = g[(j << 6) + w];
        float base = fmaf(n2m0, jf, gv);
        float m2jf = -2.0f * jf;
        #pragma unroll
        for (int k = 0; k < 16; k++)
            best[k] = fminf(best[k], fmaf(m2jf, (float)k, base));
        jf += 1.0f;
    }
    unsigned short* out = g_u + ((size_t)vol << 18) + ((size_t)d << 12);
    #pragma unroll
    for (int k = 0; k < 16; k++) {
        int h = H0 + k;
        float v = best[k] + (float)(h * h);
        out[(h << 6) + w] = (unsigned short)fminf(v, 65535.0f);
    }
}

// ------------------------------------------------------------------
// Pass 3 (D axis, windowed), fused with sdf * probs boundary reduction.
// grid (12, 64) x 256; block handles one (pair, h) slab.
__global__ void __launch_bounds__(256, 5) kPass3() {
    __shared__ float go[4096], gi[4096];
    __shared__ int   Mw[64];
    __shared__ float wsum[8];
    int pair = blockIdx.x, h = blockIdx.y;
    const unsigned short* bo = g_u + ((size_t)pair << 18)        + ((size_t)h << 6);
    const unsigned short* bi = g_u + ((size_t)(pair + 12) << 18) + ((size_t)h << 6);
    int tid = threadIdx.x;

    if (tid < 64) Mw[tid] = 0;
    __syncthreads();

    float mx = 0.f;
    #pragma unroll
    for (int r = 0; r < 16; r++) {
        int idx = (r << 8) + tid;
        int dd = idx >> 6, ww = idx & 63;
        float vo = (float)bo[((size_t)dd << 12) + ww];
        float vi = (float)bi[((size_t)dd << 12) + ww];
        mx = fmaxf(mx, fmaxf(vo, vi));
        float d2 = (float)(dd * dd);
        go[idx] = vo + d2;
        gi[idx] = vi + d2;
    }
    atomicMax(&Mw[tid & 63], __float_as_int(mx));
    __syncthreads();

    int w = tid & 63, D0 = (tid >> 6) << 4;
    float M = wredmax(__int_as_float(Mw[w]));
    int r = (int)sqrtf(M) + 1;
    int jlo = max(0, D0 - r), jhi = min(63, D0 + 15 + r);
    float n2m0 = -2.0f * (float)D0;

    float bo16[16], bi16[16];
    #pragma unroll
    for (int k = 0; k < 16; k++) { bo16[k] = 3e12f; bi16[k] = 3e12f; }
    float jf = (float)jlo;
    for (int j = jlo; j <= jhi; j++) {
        float gov = go[(j << 6) + w];
        float giv = gi[(j << 6) + w];
        float base_o = fmaf(n2m0, jf, gov);
        float base_i = fmaf(n2m0, jf, giv);
        float m2jf = -2.0f * jf;
        #pragma unroll
        for (int k = 0; k < 16; k++) {
            bo16[k] = fminf(bo16[k], fmaf(m2jf, (float)k, base_o));
            bi16[k] = fminf(bi16[k], fmaf(m2jf, (float)k, base_i));
        }
        jf += 1.0f;
    }
    float acc = 0.0f;
    const __half* pr = g_probs + ((size_t)pair << 18) + ((size_t)h << 6) + w;
    #pragma unroll
    for (int k = 0; k < 16; k++) {
        int dd = D0 + k;
        float d2 = (float)(dd * dd);
        float sdf = sqrtf(bo16[k] + d2) - sqrtf(bi16[k] + d2);
        acc = fmaf(sdf, __half2float(pr[(size_t)dd << 12]), acc);
    }
    acc = wredsum(acc);
    if ((tid & 31) == 0) wsum[tid >> 5] = acc;
    __syncthreads();
    if (tid == 0) {
        float s = 0.0f;
        #pragma unroll
        for (int i = 0; i < 8; i++) s += wsum[i];
        atomicAdd(&g_bound[pair], (double)s);
    }
}

// ------------------------------------------------------------------
__global__ void kFinal(float* __restrict__ out) {
    const double SMOOTH = 1e-5, T_ALPHA = 0.3, T_BETA = 0.7;
    double tsum = 0.0;
    for (int bc = 0; bc < 16; bc++) {
        double TP = g_TP[bc], Sp = g_Sp[bc], cnt = (double)g_cnt[bc];
        double FP = Sp - TP, FN = cnt - TP;
        tsum += (TP + SMOOTH) / (TP + T_ALPHA * FP + T_BETA * FN + SMOOTH);
    }
    double l_dice = 1.0 - tsum / 16.0;
    double l_main = g_focal / (double)NVOX;
    double bsum = 0.0;
    for (int pair = 0; pair < NPAIR; pair++) {
        int b = pair / 3, cls = pair % 3 + 1;
        unsigned c = g_cnt[b * 4 + cls];
        double contrib;
        if (c == 0u)                  contrib = 0.0;
        else if (c == (unsigned)SVOL) contrib = -g_Sp[b * 4 + cls] / (double)SVOL;
        else                          contrib = g_bound[pair] / (double)SVOL;
        bsum += contrib;
    }
    double l_bound = bsum / (12.0 + 1e-8);
    out[0] = (float)(l_dice + l_main + 0.01 * l_bound);
}

// ------------------------------------------------------------------
extern "C" void kernel_launch(void* const* d_in, const int* in_sizes, int n_in,
                              void* d_out, int out_size) {
    const float* preds   = (const float*)d_in[0];
    const int*   targets = (const int*)d_in[1];
    float*       out     = (float*)d_out;

    kZero<<<1, 64>>>();
    kFused<<<4096 + 24 * 64, 256>>>(preds, targets);
    kPass3<<<dim3(12, 64), 256>>>();
    kFinal<<<1, 1>>>(out);
}

// round 16
// speedup vs baseline: 1.1381x; 1.1381x over previous
#include <cuda_runtime.h>
#include <cuda_fp16.h>
#include <cstdint>

#define SVOL   262144        // 64^3
#define NVOX   1048576       // 4 * SVOL
#define NPAIR  12
#define INF_F  1e12f

// ---- device scratch ----
__device__ unsigned short g_u[24 * SVOL];   // pass-2 squared dists (exact ints <= 11907; 65535 = INF sentinel)
__device__ __half g_probs[NPAIR * SVOL];    // probs classes 1..3: [b][cls-1][d][h][w]
__device__ double g_Sp[16];
__device__ double g_TP[16];
__device__ unsigned g_cnt[16];
__device__ double g_focal;
__device__ double g_bound[NPAIR];
__device__ unsigned g_done;

// ------------------------------------------------------------------
__global__ void kZero() {
    int t = threadIdx.x;
    if (t < 16) { g_Sp[t] = 0.0; g_TP[t] = 0.0; g_cnt[t] = 0u; }
    if (t < NPAIR) g_bound[t] = 0.0;
    if (t == 0) { g_focal = 0.0; g_done = 0u; }
}

__device__ __forceinline__ float wredsum(float v) {
    v += __shfl_xor_sync(0xffffffffu, v, 16);
    v += __shfl_xor_sync(0xffffffffu, v, 8);
    v += __shfl_xor_sync(0xffffffffu, v, 4);
    v += __shfl_xor_sync(0xffffffffu, v, 2);
    v += __shfl_xor_sync(0xffffffffu, v, 1);
    return v;
}
__device__ __forceinline__ float wredmax(float v) {
    v = fmaxf(v, __shfl_xor_sync(0xffffffffu, v, 16));
    v = fmaxf(v, __shfl_xor_sync(0xffffffffu, v, 8));
    v = fmaxf(v, __shfl_xor_sync(0xffffffffu, v, 4));
    v = fmaxf(v, __shfl_xor_sync(0xffffffffu, v, 2));
    v = fmaxf(v, __shfl_xor_sync(0xffffffffu, v, 1));
    return v;
}

__device__ __forceinline__ float nearestSq(unsigned long long m, int i) {
    if (m == 0ull) return INF_F;
    unsigned long long lo = m << (63 - i);   // bits j<=i
    unsigned long long hi = m >> i;          // bits j>=i
    int dup = lo ? __clzll(lo) : 1000;
    int ddn = hi ? (__ffsll(hi) - 1) : 1000;
    int d = min(dup, ddn);
    return (float)(d * d);
}

// ------------------------------------------------------------------
// Fused kernel: blocks [0,4096) do softmax/focal/Tversky stats;
// blocks [4096, 4096+1536) do pass1+pass2 EDT for one (vol, d) plane.
__global__ void __launch_bounds__(256) kFused(const float* __restrict__ preds,
                                              const int* __restrict__ targets) {
    __shared__ float g[4096];   // pass12: g[h*64+w] = f(h,w) + h^2
    __shared__ int   Mw[64];
    __shared__ float ssp[4], stp[4], sfo;
    __shared__ unsigned scnt[4];

    int tid = threadIdx.x, lane = tid & 31;

    if (blockIdx.x < 4096) {
        // ================= stats role =================
        if (tid < 4) { ssp[tid] = 0.f; stp[tid] = 0.f; scnt[tid] = 0u; }
        if (tid == 0) sfo = 0.f;
        __syncthreads();

        int v = blockIdx.x * 256 + tid;
        int b = v >> 18;
        int s = v & (SVOL - 1);

        const float* p = preds + ((size_t)b << 20) + s;
        float x0 = p[0], x1 = p[SVOL], x2 = p[2 * SVOL], x3 = p[3 * SVOL];
        float m = fmaxf(fmaxf(x0, x1), fmaxf(x2, x3));
        float e0 = __expf(x0 - m), e1 = __expf(x1 - m);
        float e2 = __expf(x2 - m), e3 = __expf(x3 - m);
        float Z = e0 + e1 + e2 + e3;
        float inv = 1.0f / Z;
        float p0 = e0 * inv, p1 = e1 * inv, p2 = e2 * inv, p3 = e3 * inv;

        int t = targets[v];
        float lz = __logf(Z);
        float xt = (t == 0) ? x0 : (t == 1) ? x1 : (t == 2) ? x2 : x3;
        float pt = (t == 0) ? p0 : (t == 1) ? p1 : (t == 2) ? p2 : p3;
        float ce = -(xt - m - lz);
        float om = 1.0f - pt;
        float fo = om * om * ce;

        size_t pb = (size_t)(b * 3) * SVOL + s;
        g_probs[pb]            = __float2half(p1);
        g_probs[pb + SVOL]     = __float2half(p2);
        g_probs[pb + 2 * SVOL] = __float2half(p3);

        float sp[4] = { p0, p1, p2, p3 };
        #pragma unroll
        for (int c = 0; c < 4; c++) {
            unsigned bal = __ballot_sync(0xffffffffu, t == c);
            float spv = wredsum(sp[c]);
            float tpv = wredsum((t == c) ? pt : 0.0f);
            if (lane == 0) {
                atomicAdd(&ssp[c], spv);
                atomicAdd(&stp[c], tpv);
                atomicAdd(&scnt[c], (unsigned)__popc(bal));
            }
        }
        float fr = wredsum(fo);
        if (lane == 0) atomicAdd(&sfo, fr);
        __syncthreads();

        if (tid < 4) {
            atomicAdd(&g_Sp[b * 4 + tid], (double)ssp[tid]);
            atomicAdd(&g_TP[b * 4 + tid], (double)stp[tid]);
            atomicAdd(&g_cnt[b * 4 + tid], scnt[tid]);
        }
        if (tid == 4) atomicAdd(&g_focal, (double)sfo);
        return;
    }

    // ================= pass1 + pass2 role =================
    int bb = blockIdx.x - 4096;           // 0..1535
    int vol = bb >> 6, d = bb & 63;       // vol 0..23
    int v12 = (vol >= 12) ? vol - 12 : vol;
    int b = v12 / 3, cls = v12 % 3 + 1;
    bool invm = (vol >= 12);
    const int* tp = targets + ((size_t)b << 18) + ((size_t)d << 12);
    int wid = tid >> 5;

    if (tid < 64) Mw[tid] = 0;
    __syncthreads();

    // pass 1 (W axis): each warp handles lines h = wid*8 + i
    float mx0 = 0.f, mx1 = 0.f;
    #pragma unroll
    for (int i = 0; i < 8; i++) {
        int h = wid * 8 + i;
        int t0 = tp[(h << 6) + lane];
        int t1 = tp[(h << 6) + lane + 32];
        unsigned b0 = __ballot_sync(0xffffffffu, t0 == cls);
        unsigned b1 = __ballot_sync(0xffffffffu, t1 == cls);
        unsigned long long mm = (unsigned long long)b0 | ((unsigned long long)b1 << 32);
        if (invm) mm = ~mm;
        float f0 = nearestSq(mm, lane);
        float f1 = nearestSq(mm, lane + 32);
        float hh = (float)(h * h);
        g[(h << 6) + lane]      = f0 + hh;
        g[(h << 6) + lane + 32] = f1 + hh;
        mx0 = fmaxf(mx0, f0);
        mx1 = fmaxf(mx1, f1);
    }
    atomicMax(&Mw[lane],      __float_as_int(mx0));
    atomicMax(&Mw[lane + 32], __float_as_int(mx1));
    __syncthreads();

    // pass 2 (H axis): windowed min-plus; thread outputs h in [H0, H0+15]
    int w = tid & 63, H0 = (tid >> 6) << 4;
    float M = wredmax(__int_as_float(Mw[w]));
    int r = (int)sqrtf(M) + 1;
    int jlo = max(0, H0 - r), jhi = min(63, H0 + 15 + r);
    float n2m0 = -2.0f * (float)H0;

    float best[16];
    #pragma unroll
    for (int k = 0; k < 16; k++) best[k] = 3e12f;
    float jf = (float)jlo;
    for (int j = jlo; j <= jhi; j++) {
        float gv = g[(j << 6) + w];
        float base = fmaf(n2m0, jf, gv);
        float m2jf = -2.0f * jf;
        #pragma unroll
        for (int k = 0; k < 16; k++)
            best[k] = fminf(best[k], fmaf(m2jf, (float)k, base));
        jf += 1.0f;
    }
    unsigned short* out = g_u + ((size_t)vol << 18) + ((size_t)d << 12);
    #pragma unroll
    for (int k = 0; k < 16; k++) {
        int h = H0 + k;
        float v = best[k] + (float)(h * h);
        out[(h << 6) + w] = (unsigned short)fminf(v, 65535.0f);
    }
}

// ------------------------------------------------------------------
// Pass 3 (D axis, windowed), fused with sdf * probs boundary reduction,
// and with the final loss assembly done by the LAST block to finish.
// grid (12, 64) x 256; block handles one (pair, h) slab.
__global__ void __launch_bounds__(256, 5) kPass3(float* __restrict__ outp) {
    __shared__ float go[4096], gi[4096];
    __shared__ int   Mw[64];
    __shared__ float wsum[8];
    __shared__ int   amLast;
    __shared__ double sh_tv[16], sh_bd[NPAIR];
    int pair = blockIdx.x, h = blockIdx.y;
    const unsigned short* bo = g_u + ((size_t)pair << 18)        + ((size_t)h << 6);
    const unsigned short* bi = g_u + ((size_t)(pair + 12) << 18) + ((size_t)h << 6);
    int tid = threadIdx.x;

    if (tid < 64) Mw[tid] = 0;
    __syncthreads();

    float mx = 0.f;
    #pragma unroll
    for (int r = 0; r < 16; r++) {
        int idx = (r << 8) + tid;
        int dd = idx >> 6, ww = idx & 63;
        float vo = (float)bo[((size_t)dd << 12) + ww];
        float vi = (float)bi[((size_t)dd << 12) + ww];
        mx = fmaxf(mx, fmaxf(vo, vi));
        float d2 = (float)(dd * dd);
        go[idx] = vo + d2;
        gi[idx] = vi + d2;
    }
    atomicMax(&Mw[tid & 63], __float_as_int(mx));
    __syncthreads();

    int w = tid & 63, D0 = (tid >> 6) << 4;
    float M = wredmax(__int_as_float(Mw[w]));
    int r = (int)sqrtf(M) + 1;
    int jlo = max(0, D0 - r), jhi = min(63, D0 + 15 + r);
    float n2m0 = -2.0f * (float)D0;

    float bo16[16], bi16[16];
    #pragma unroll
    for (int k = 0; k < 16; k++) { bo16[k] = 3e12f; bi16[k] = 3e12f; }
    float jf = (float)jlo;
    for (int j = jlo; j <= jhi; j++) {
        float gov = go[(j << 6) + w];
        float giv = gi[(j << 6) + w];
        float base_o = fmaf(n2m0, jf, gov);
        float base_i = fmaf(n2m0, jf, giv);
        float m2jf = -2.0f * jf;
        #pragma unroll
        for (int k = 0; k < 16; k++) {
            bo16[k] = fminf(bo16[k], fmaf(m2jf, (float)k, base_o));
            bi16[k] = fminf(bi16[k], fmaf(m2jf, (float)k, base_i));
        }
        jf += 1.0f;
    }
    float acc = 0.0f;
    const __half* pr = g_probs + ((size_t)pair << 18) + ((size_t)h << 6) + w;
    #pragma unroll
    for (int k = 0; k < 16; k++) {
        int dd = D0 + k;
        float d2 = (float)(dd * dd);
        float sdf = sqrtf(bo16[k] + d2) - sqrtf(bi16[k] + d2);
        acc = fmaf(sdf, __half2float(pr[(size_t)dd << 12]), acc);
    }
    acc = wredsum(acc);
    if ((tid & 31) == 0) wsum[tid >> 5] = acc;
    __syncthreads();
    if (tid == 0) {
        float s = 0.0f;
        #pragma unroll
        for (int i = 0; i < 8; i++) s += wsum[i];
        atomicAdd(&g_bound[pair], (double)s);
        __threadfence();
        unsigned old = atomicAdd(&g_done, 1u);
        amLast = (old == (12u * 64u - 1u)) ? 1 : 0;
    }
    __syncthreads();
    if (!amLast) return;

    // ---- last block: assemble the final loss (parallel loads) ----
    const double SMOOTH = 1e-5, T_ALPHA = 0.3, T_BETA = 0.7;
    if (tid < 16) {
        double TP = g_TP[tid], Sp = g_Sp[tid], cnt = (double)g_cnt[tid];
        double FP = Sp - TP, FN = cnt - TP;
        sh_tv[tid] = (TP + SMOOTH) / (TP + T_ALPHA * FP + T_BETA * FN + SMOOTH);
    } else if (tid >= 32 && tid < 32 + NPAIR) {
        int pr2 = tid - 32;
        int b = pr2 / 3, cls = pr2 % 3 + 1;
        unsigned c = g_cnt[b * 4 + cls];
        double contrib;
        if (c == 0u)                  contrib = 0.0;
        else if (c == (unsigned)SVOL) contrib = -g_Sp[b * 4 + cls] / (double)SVOL;
        else                          contrib = g_bound[pr2] / (double)SVOL;
        sh_bd[pr2] = contrib;
    }
    __syncthreads();
    if (tid == 0) {
        double tsum = 0.0;
        #pragma unroll
        for (int i = 0; i < 16; i++) tsum += sh_tv[i];
        double l_dice = 1.0 - tsum / 16.0;
        double l_main = g_focal / (double)NVOX;
        double bsum = 0.0;
        #pragma unroll
        for (int i = 0; i < NPAIR; i++) bsum += sh_bd[i];
        double l_bound = bsum / (12.0 + 1e-8);
        outp[0] = (float)(l_dice + l_main + 0.01 * l_bound);
    }
}

// ------------------------------------------------------------------
extern "C" void kernel_launch(void* const* d_in, const int* in_sizes, int n_in,
                              void* d_out, int out_size) {
    const float* preds   = (const float*)d_in[0];
    const int*   targets = (const int*)d_in[1];
    float*       out     = (float*)d_out;

    kZero<<<1, 64>>>();
    kFused<<<4096 + 24 * 64, 256>>>(preds, targets);
    kPass3<<<dim3(12, 64), 256>>>(out);
}